// round 14
// baseline (speedup 1.0000x reference)
#include <cuda_runtime.h>
#include <cuda_bf16.h>
#include <math.h>

// Problem constants
#define N    2048
#define DH   256
#define DK   64
#define FF   32

typedef unsigned long long u64;
typedef unsigned int u32;

// ---------------------------------------------------------------------------
// f32x2 packed helpers (portable PTX, sm_100+)
// ---------------------------------------------------------------------------
__device__ __forceinline__ u64 pack2(float lo, float hi) {
    u64 r;
    asm("mov.b64 %0, {%1, %2};" : "=l"(r) : "f"(lo), "f"(hi));
    return r;
}
__device__ __forceinline__ void unpack2(u64 v, float& lo, float& hi) {
    asm("mov.b64 {%0, %1}, %2;" : "=f"(lo), "=f"(hi) : "l"(v));
}
__device__ __forceinline__ u64 fma2(u64 a, u64 b, u64 c) {
    u64 d;
    asm("fma.rn.f32x2 %0, %1, %2, %3;" : "=l"(d) : "l"(a), "l"(b), "l"(c));
    return d;
}
__device__ __forceinline__ u64 dup2(float v) { return pack2(v, v); }

// tf32 truncation (portable, sm_80+)
__device__ __forceinline__ u32 f2tf32(float x) {
    u32 r;
    asm("cvt.rna.tf32.f32 %0, %1;" : "=r"(r) : "f"(x));
    return r;
}

// m16n8k8 tf32 mma (portable, sm_80+). D += A*B, fp32 accumulate.
__device__ __forceinline__ void mma_tf32(float d[4], u32 a0, u32 a1, u32 a2,
                                         u32 a3, u32 b0, u32 b1) {
    asm volatile(
        "mma.sync.aligned.m16n8k8.row.col.f32.tf32.tf32.f32 "
        "{%0,%1,%2,%3}, {%4,%5,%6,%7}, {%8,%9}, {%0,%1,%2,%3};"
        : "+f"(d[0]), "+f"(d[1]), "+f"(d[2]), "+f"(d[3])
        : "r"(a0), "r"(a1), "r"(a2), "r"(a3), "r"(b0), "r"(b1));
}

// ---------------------------------------------------------------------------
// Scratch (no cudaMalloc allowed)
// ---------------------------------------------------------------------------
#define KSPLIT 16
__device__ float g_q[N * DK];              // Q(x_j): (N, 64)
__device__ float g_k[N * DK];              // K(x_i): (N, 64)
__device__ float g_v[N * DH];              // V(x_j): (N, 256)
__device__ float g_scores[(size_t)N * N];  // k @ q^T
__device__ float g_p[(size_t)N * N];       // logits, then softmax P (in-place)
__device__ float g_part[KSPLIT * (size_t)N * DH];  // split-K partials for P@V

// ---------------------------------------------------------------------------
// Kernel A: q/k/v projections (unchanged from best)
// ---------------------------------------------------------------------------
#define A_ROWS 16
__global__ void __launch_bounds__(256) proj_kernel(
    const float* __restrict__ x,
    const float* __restrict__ Wq, const float* __restrict__ bq,
    const float* __restrict__ Wk, const float* __restrict__ bk,
    const float* __restrict__ Wv, const float* __restrict__ bv)
{
    __shared__ float xs[A_ROWS * DH];
    const int tid = threadIdx.x;
    const int r0  = blockIdx.x * A_ROWS;

    for (int idx = tid; idx < A_ROWS * DH; idx += 256)
        xs[idx] = x[(size_t)r0 * DH + idx];
    __syncthreads();

    for (int g = tid; g < 384; g += 256) {
        const float* W; const float* b; float* out;
        int ld, col;
        if (g < 64)        { W = Wq; b = bq; out = g_q; ld = DK; col = g; }
        else if (g < 128)  { W = Wk; b = bk; out = g_k; ld = DK; col = g - 64; }
        else               { W = Wv; b = bv; out = g_v; ld = DH; col = g - 128; }

        float acc[A_ROWS];
        const float bb = b[col];
#pragma unroll
        for (int r = 0; r < A_ROWS; r++) acc[r] = bb;

#pragma unroll 8
        for (int k = 0; k < DH; k++) {
            const float w = __ldg(&W[k * ld + col]);
#pragma unroll
            for (int r = 0; r < A_ROWS; r++)
                acc[r] = fmaf(xs[r * DH + k], w, acc[r]);
        }
#pragma unroll
        for (int r = 0; r < A_ROWS; r++)
            out[(size_t)(r0 + r) * ld + col] = acc[r];
    }
}

// ---------------------------------------------------------------------------
// Kernel B: scores = k @ q^T (unchanged from best)
// ---------------------------------------------------------------------------
__global__ void __launch_bounds__(256) scores_kernel()
{
    __shared__ float ks[64 * 68];
    __shared__ float qs[64 * 68];
    const int tid = threadIdx.x;
    const int j0 = blockIdx.x * 64;
    const int i0 = blockIdx.y * 64;

    for (int idx = tid; idx < 64 * 64; idx += 256) {
        const int row = idx >> 6;
        const int c   = idx & 63;
        ks[c * 68 + row] = g_k[(size_t)(i0 + row) * DK + c];
        qs[c * 68 + row] = g_q[(size_t)(j0 + row) * DK + c];
    }
    __syncthreads();

    const int ty = tid >> 4, tx = tid & 15;
    u64 acc[4][2];
#pragma unroll
    for (int r = 0; r < 4; r++) { acc[r][0] = 0ULL; acc[r][1] = 0ULL; }

#pragma unroll 8
    for (int c = 0; c < 64; c++) {
        const float4 a4 = *reinterpret_cast<const float4*>(&ks[c * 68 + ty * 4]);
        const ulonglong2 bq2 = *reinterpret_cast<const ulonglong2*>(&qs[c * 68 + tx * 4]);
        u64 ad[4] = { dup2(a4.x), dup2(a4.y), dup2(a4.z), dup2(a4.w) };
        u64 bb[2] = { bq2.x, bq2.y };
#pragma unroll
        for (int r = 0; r < 4; r++)
#pragma unroll
            for (int cc = 0; cc < 2; cc++)
                acc[r][cc] = fma2(ad[r], bb[cc], acc[r][cc]);
    }

#pragma unroll
    for (int r = 0; r < 4; r++) {
        float x0, x1, x2, x3;
        unpack2(acc[r][0], x0, x1);
        unpack2(acc[r][1], x2, x3);
        float4 o = make_float4(x0, x1, x2, x3);
        *reinterpret_cast<float4*>(
            &g_scores[(size_t)(i0 + ty * 4 + r) * N + j0 + tx * 4]) = o;
    }
}

// ---------------------------------------------------------------------------
// Kernel C1: per-pair MLP -> raw logits, layer-2 on tensor cores via
// mma.sync m16n8k8 tf32 with 3-term hi/lo split (error ~2^-21, ~fp32).
//
// One block (8 warps) per row i. Each warp: 16 tiles of 16 j (M=16, N=32,
// K=32 GEMM per tile = 4 kchunks x 4 ntiles x 3 terms = 48 mma).
// Layer-1 h1 is computed directly in A-fragment layout (lane (g,tig) needs
// exactly h1[j in {g,g+8}][ii = 4m+tig]) -> no smem staging at all.
// W2 hi/lo B-fragments live in registers for the whole kernel.
// Epilogue relu(+b2)*W3 in registers + shfl-reduce over tig.
// b3 is softmax-invariant and dropped.
// ---------------------------------------------------------------------------
__global__ void __launch_bounds__(256) mlp_mma_kernel(
    const float* __restrict__ adj,  const float* __restrict__ dense,
    const float* __restrict__ W1,   const float* __restrict__ b1,
    const float* __restrict__ W2,   const float* __restrict__ b2,
    const float* __restrict__ W3)
{
    const int tid  = threadIdx.x;
    const int wid  = tid >> 5;
    const int lane = tid & 31;
    const int g    = lane >> 2;     // group id (0..7)
    const int tig  = lane & 3;      // thread in group (0..3)
    const int i    = blockIdx.x;

    // Per-lane W1 coefficients for its 8 ii values: ii = 4m + tig.
    float c0[8], c1[8], c2[8], bb1[8];
#pragma unroll
    for (int m = 0; m < 8; m++) {
        const int ii = 4 * m + tig;
        c0[m]  = __ldg(&W1[ii]);
        c1[m]  = __ldg(&W1[FF + ii]);
        c2[m]  = __ldg(&W1[2 * FF + ii]);
        bb1[m] = __ldg(&b1[ii]);
    }

    // B fragments (W2, [ii=k][o=n] row-major). b0: k=kc*8+tig, b1: k=+4; n=nt*8+g.
    u32 bhi[4][4][2], blo[4][4][2];
#pragma unroll
    for (int nt = 0; nt < 4; nt++) {
        const int n = nt * 8 + g;
#pragma unroll
        for (int kc = 0; kc < 4; kc++) {
#pragma unroll
            for (int h = 0; h < 2; h++) {
                const int k = kc * 8 + tig + 4 * h;
                const float w = __ldg(&W2[k * FF + n]);
                const u32 whi = f2tf32(w);
                bhi[nt][kc][h] = whi;
                blo[nt][kc][h] = f2tf32(w - __uint_as_float(whi));
            }
        }
    }

    // Epilogue constants for this lane's D columns: col = nt*8 + 2*tig + q.
    float eb2[4][2], ew3[4][2];
#pragma unroll
    for (int nt = 0; nt < 4; nt++) {
#pragma unroll
        for (int q = 0; q < 2; q++) {
            const int col = nt * 8 + 2 * tig + q;
            eb2[nt][q] = __ldg(&b2[col]);
            ew3[nt][q] = __ldg(&W3[col]);
        }
    }

    const float* srow = g_scores + (size_t)i * N;
    const float* arow = adj      + (size_t)i * N;
    const float* drow = dense    + (size_t)i * N;
    float* prow = g_p + (size_t)i * N;

    for (int it = 0; it < 16; it++) {
        const int j0 = (it * 8 + wid) * 16;

        // Inputs for 16 j: lane loads j0 + (lane&15), shfl distributes.
        const int jl = j0 + (lane & 15);
        const float sv = srow[jl];
        const float av = arow[jl];
        const float dv = drow[jl];
        const float sg  = __shfl_sync(0xffffffffu, sv, g);
        const float ag  = __shfl_sync(0xffffffffu, av, g);
        const float dg  = __shfl_sync(0xffffffffu, dv, g);
        const float sg8 = __shfl_sync(0xffffffffu, sv, g + 8);
        const float ag8 = __shfl_sync(0xffffffffu, av, g + 8);
        const float dg8 = __shfl_sync(0xffffffffu, dv, g + 8);

        // Layer 1 directly into A-fragment registers: rows {g, g+8}, ii=4m+tig.
        u32 ahi[2][8], alo[2][8];
#pragma unroll
        for (int jr = 0; jr < 2; jr++) {
            const float s_ = jr ? sg8 : sg;
            const float a_ = jr ? ag8 : ag;
            const float d_ = jr ? dg8 : dg;
#pragma unroll
            for (int m = 0; m < 8; m++) {
                float t = fmaf(d_, c2[m], bb1[m]);
                t = fmaf(a_, c1[m], t);
                t = fmaf(s_, c0[m], t);
                t = fmaxf(t, 0.0f);
                const u32 thi = f2tf32(t);
                ahi[jr][m] = thi;
                alo[jr][m] = f2tf32(t - __uint_as_float(thi));
            }
        }

        // Layer 2 GEMM: D[16 x 32] += A[16 x 32] * W2[32 x 32], 3-term split.
        float D[4][4];
#pragma unroll
        for (int nt = 0; nt < 4; nt++)
#pragma unroll
            for (int q = 0; q < 4; q++) D[nt][q] = 0.0f;

#pragma unroll
        for (int kc = 0; kc < 4; kc++) {
            const u32 a0h = ahi[0][2 * kc],     a1h = ahi[1][2 * kc];
            const u32 a2h = ahi[0][2 * kc + 1], a3h = ahi[1][2 * kc + 1];
            const u32 a0l = alo[0][2 * kc],     a1l = alo[1][2 * kc];
            const u32 a2l = alo[0][2 * kc + 1], a3l = alo[1][2 * kc + 1];
#pragma unroll
            for (int nt = 0; nt < 4; nt++) {
                mma_tf32(D[nt], a0h, a1h, a2h, a3h,
                         bhi[nt][kc][0], bhi[nt][kc][1]);   // hi*hi
                mma_tf32(D[nt], a0h, a1h, a2h, a3h,
                         blo[nt][kc][0], blo[nt][kc][1]);   // hi*lo
                mma_tf32(D[nt], a0l, a1l, a2l, a3l,
                         bhi[nt][kc][0], bhi[nt][kc][1]);   // lo*hi
            }
        }

        // Epilogue: logit[j] = sum_o relu(H2 + b2[o]) * W3[o].
        // D rows: {g, g+8}; cols: nt*8 + 2*tig + q.
        float lg0 = 0.0f, lg1 = 0.0f;
#pragma unroll
        for (int nt = 0; nt < 4; nt++) {
#pragma unroll
            for (int q = 0; q < 2; q++) {
                lg0 = fmaf(fmaxf(D[nt][q]     + eb2[nt][q], 0.0f), ew3[nt][q], lg0);
                lg1 = fmaf(fmaxf(D[nt][2 + q] + eb2[nt][q], 0.0f), ew3[nt][q], lg1);
            }
        }
        // Reduce over the 4 threads of the group (tig axis).
        lg0 += __shfl_xor_sync(0xffffffffu, lg0, 1);
        lg0 += __shfl_xor_sync(0xffffffffu, lg0, 2);
        lg1 += __shfl_xor_sync(0xffffffffu, lg1, 1);
        lg1 += __shfl_xor_sync(0xffffffffu, lg1, 2);

        if (tig == 0) {
            prow[j0 + g]     = lg0;
            prow[j0 + g + 8] = lg1;
        }
    }
}

// ---------------------------------------------------------------------------
// Kernel C2: in-place row softmax over g_p (unchanged from best)
// ---------------------------------------------------------------------------
__global__ void __launch_bounds__(256) softmax_kernel()
{
    __shared__ float redbuf[8];
    const int tid = threadIdx.x;
    const int i   = blockIdx.x;
    float4* row = reinterpret_cast<float4*>(g_p + (size_t)i * N);

    float4 x0 = row[tid];
    float4 x1 = row[tid + 256];

    float lmax = fmaxf(fmaxf(fmaxf(x0.x, x0.y), fmaxf(x0.z, x0.w)),
                       fmaxf(fmaxf(x1.x, x1.y), fmaxf(x1.z, x1.w)));
#pragma unroll
    for (int off = 16; off > 0; off >>= 1)
        lmax = fmaxf(lmax, __shfl_xor_sync(0xffffffffu, lmax, off));
    if ((tid & 31) == 0) redbuf[tid >> 5] = lmax;
    __syncthreads();
    float m;
    {
        float v = redbuf[tid & 7];
#pragma unroll
        for (int off = 4; off > 0; off >>= 1)
            v = fmaxf(v, __shfl_xor_sync(0xffffffffu, v, off));
        m = v;
    }
    __syncthreads();

    x0.x = __expf(x0.x - m); x0.y = __expf(x0.y - m);
    x0.z = __expf(x0.z - m); x0.w = __expf(x0.w - m);
    x1.x = __expf(x1.x - m); x1.y = __expf(x1.y - m);
    x1.z = __expf(x1.z - m); x1.w = __expf(x1.w - m);

    float lsum = (x0.x + x0.y) + (x0.z + x0.w) + (x1.x + x1.y) + (x1.z + x1.w);
#pragma unroll
    for (int off = 16; off > 0; off >>= 1)
        lsum += __shfl_xor_sync(0xffffffffu, lsum, off);
    if ((tid & 31) == 0) redbuf[tid >> 5] = lsum;
    __syncthreads();
    float stot;
    {
        float v = redbuf[tid & 7];
#pragma unroll
        for (int off = 4; off > 0; off >>= 1)
            v += __shfl_xor_sync(0xffffffffu, v, off);
        stot = v;
    }
    const float rinv = 1.0f / stot;

    x0.x *= rinv; x0.y *= rinv; x0.z *= rinv; x0.w *= rinv;
    x1.x *= rinv; x1.y *= rinv; x1.z *= rinv; x1.w *= rinv;
    row[tid]       = x0;
    row[tid + 256] = x1;
}

// ---------------------------------------------------------------------------
// Kernel D: feature = P @ v via split-K (16 ways) + reduce (unchanged)
// ---------------------------------------------------------------------------
#define AV_BK 16
__global__ void __launch_bounds__(256, 2) av_split_kernel()
{
    __shared__ float ps[AV_BK][132];
    __shared__ float vs[AV_BK][132];

    const int tid = threadIdx.x;
    const int j0    = blockIdx.x * 128;
    const int i0    = blockIdx.y * 128;
    const int kbase = blockIdx.z * (N / KSPLIT);
    const int ty = tid >> 4, tx = tid & 15;

    u64 acc[8][4];
#pragma unroll
    for (int r = 0; r < 8; r++)
#pragma unroll
        for (int c = 0; c < 4; c++) acc[r][c] = 0ULL;

    for (int kt = 0; kt < N / KSPLIT; kt += AV_BK) {
#pragma unroll
        for (int l = 0; l < 8; l++) {
            const int idx = l * 256 + tid;
            const int ii = idx >> 4;
            const int kk = idx & 15;
            ps[kk][ii] = g_p[(size_t)(i0 + ii) * N + kbase + kt + kk];
        }
#pragma unroll
        for (int l = 0; l < 8; l++) {
            const int idx = l * 256 + tid;
            const int kk = idx >> 7;
            const int jj = idx & 127;
            vs[kk][jj] = g_v[(size_t)(kbase + kt + kk) * DH + j0 + jj];
        }
        __syncthreads();

#pragma unroll
        for (int kk = 0; kk < AV_BK; kk++) {
            const float4 a0 = *reinterpret_cast<const float4*>(&ps[kk][ty * 8]);
            const float4 a1 = *reinterpret_cast<const float4*>(&ps[kk][ty * 8 + 4]);
            const ulonglong2 b0 = *reinterpret_cast<const ulonglong2*>(&vs[kk][tx * 8]);
            const ulonglong2 b1 = *reinterpret_cast<const ulonglong2*>(&vs[kk][tx * 8 + 4]);
            u64 ad[8] = { dup2(a0.x), dup2(a0.y), dup2(a0.z), dup2(a0.w),
                          dup2(a1.x), dup2(a1.y), dup2(a1.z), dup2(a1.w) };
            u64 bb[4] = { b0.x, b0.y, b1.x, b1.y };
#pragma unroll
            for (int r = 0; r < 8; r++)
#pragma unroll
                for (int c = 0; c < 4; c++)
                    acc[r][c] = fma2(ad[r], bb[c], acc[r][c]);
        }
        __syncthreads();
    }

    float* dst = g_part + (size_t)blockIdx.z * ((size_t)N * DH);
#pragma unroll
    for (int r = 0; r < 8; r++) {
        const int row = i0 + ty * 8 + r;
        float x0, x1, x2, x3, x4, x5, x6, x7;
        unpack2(acc[r][0], x0, x1);
        unpack2(acc[r][1], x2, x3);
        unpack2(acc[r][2], x4, x5);
        unpack2(acc[r][3], x6, x7);
        float4* d4 = reinterpret_cast<float4*>(&dst[(size_t)row * DH + j0 + tx * 8]);
        d4[0] = make_float4(x0, x1, x2, x3);
        d4[1] = make_float4(x4, x5, x6, x7);
    }
}

// Deterministic fixed-order reduction of the 16 split-K partials.
__global__ void __launch_bounds__(256) av_reduce_kernel(float* __restrict__ out)
{
    const int idx = blockIdx.x * 256 + threadIdx.x;
    const float4* p = reinterpret_cast<const float4*>(g_part);
    float4 s = p[idx];
#pragma unroll
    for (int k = 1; k < KSPLIT; k++) {
        const float4 v = p[(size_t)k * (N * DH / 4) + idx];
        s.x += v.x; s.y += v.y; s.z += v.z; s.w += v.w;
    }
    reinterpret_cast<float4*>(out)[idx] = s;
}

// ---------------------------------------------------------------------------
// Launch. Inputs (metadata order):
//  0 x, 1 adj, 2 dense, 3 Wq, 4 bq, 5 Wk, 6 bk, 7 Wv, 8 bv,
//  9 W1, 10 b1, 11 W2, 12 b2, 13 W3, 14 b3 (softmax-invariant, unused)
// ---------------------------------------------------------------------------
extern "C" void kernel_launch(void* const* d_in, const int* in_sizes, int n_in,
                              void* d_out, int out_size)
{
    const float* x     = (const float*)d_in[0];
    const float* adj   = (const float*)d_in[1];
    const float* dense = (const float*)d_in[2];
    const float* Wq    = (const float*)d_in[3];
    const float* bq    = (const float*)d_in[4];
    const float* Wk    = (const float*)d_in[5];
    const float* bk    = (const float*)d_in[6];
    const float* Wv    = (const float*)d_in[7];
    const float* bv    = (const float*)d_in[8];
    const float* W1    = (const float*)d_in[9];
    const float* b1    = (const float*)d_in[10];
    const float* W2    = (const float*)d_in[11];
    const float* b2    = (const float*)d_in[12];
    const float* W3    = (const float*)d_in[13];
    float* out = (float*)d_out;

    proj_kernel<<<N / A_ROWS, 256>>>(x, Wq, bq, Wk, bk, Wv, bv);
    scores_kernel<<<dim3(N / 64, N / 64), 256>>>();
    mlp_mma_kernel<<<N, 256>>>(adj, dense, W1, b1, W2, b2, W3);
    softmax_kernel<<<N, 256>>>();
    av_split_kernel<<<dim3(2, 16, KSPLIT), 256>>>();
    av_reduce_kernel<<<N * DH / 4 / 256, 256>>>(out);
}